// round 15
// baseline (speedup 1.0000x reference)
#include <cuda_runtime.h>
#include <math.h>
#include <stdint.h>

#define BB 2
#define NN 512
#define DD 64
#define HH 8
#define DHH 128

// ----------------- k_edge smem layout (floats) -----------------
#define OFF_ELOG   0        // 8*520 = 4160
#define OFF_WEP    4160     // 512
#define OFF_WGP    4672     // 512
#define OFF_Q      5184     // 64
#define OFF_SE     5248     // 8
#define OFF_CE     5256     // 8
#define OFF_SG     5264     // 8
#define OFF_CG     5272     // 8
#define OFF_CENT   5280     // 8
#define OFF_WPART  5288     // 64
#define OFF_ET     5352     // 128 x 68
#define OFF_KT     14056    // 128 x 68
#define EDGE_SMEM_FLOATS 22760
#define EDGE_SMEM_BYTES  (EDGE_SMEM_FLOATS*4)   // 91040 B

// ----------------- K3 v2 (128 thr, 64-edge tile) smem (floats) -----------
#define KA_OFF    0          // sA 64 x 68 fp32   (4352)
#define KH_OFF    4352       // sH 64 x 132 tf32  (8448)
#define KB1_OFF   12800      // 128
#define KB2_OFF   12928      // 64
#define KWOE_OFF  12992      // 512
#define KEL_OFF   13504      // 512 (Elog slice [8][64])
#define KG1_OFF   14016      // 64
#define KBE1_OFF  14080      // 64
#define KG2_OFF   14144      // 64
#define KBE2_OFF  14208      // 64
#define K3_SMEM_FLOATS 14272
#define K3_SMEM_BYTES  (K3_SMEM_FLOATS*4)   // 57088 B -> 3 CTAs/SM

__device__ __align__(16) float g_n1[BB*NN*DD];
__device__ __align__(16) float g_q [BB*NN*DD];
__device__ __align__(16) float g_k [BB*NN*DD];
__device__ __align__(16) float g_vt[BB*HH*8*NN];
__device__ __align__(16) float g_vc[BB*NN*DD];
__device__ __align__(16) float g_elog[(size_t)BB*HH*NN*NN];
__device__ __align__(16) uint32_t g_w1p[64*DHH];   // permuted tf32 W1
__device__ __align__(16) uint32_t g_w2p[DHH*64];   // permuted tf32 W2

__device__ __forceinline__ uint32_t f2tf32(float x) {
    uint32_t r;
    asm("cvt.rna.tf32.f32 %0, %1;" : "=r"(r) : "f"(x));
    return r;
}

__device__ __forceinline__ void mma_tf32(float& c0, float& c1, float& c2, float& c3,
                                         uint32_t a0, uint32_t a1,
                                         uint32_t a2, uint32_t a3,
                                         uint32_t b0, uint32_t b1) {
    asm volatile(
        "mma.sync.aligned.m16n8k8.row.col.f32.tf32.tf32.f32 "
        "{%0,%1,%2,%3},{%4,%5,%6,%7},{%8,%9},{%0,%1,%2,%3};"
        : "+f"(c0), "+f"(c1), "+f"(c2), "+f"(c3)
        : "r"(a0), "r"(a1), "r"(a2), "r"(a3), "r"(b0), "r"(b1));
}

// ---------------------------------------------------------------------------
// K0: convert + permute MLP weights to tf32 in gmem (done once per launch).
// W1: pos = k*128 + nc*32 + g*4 + nt  (u = nc*32 + nt*8 + g)
// W2: pos = u*64  + nc*32 + g*4 + nt  (c = nc*32 + nt*8 + g)
// ---------------------------------------------------------------------------
__global__ void k_w_prep(const float* __restrict__ W1, const float* __restrict__ W2)
{
    int t = blockIdx.x*256 + threadIdx.x;
    if (t < 64*DHH) {
        int k = t >> 7, u = t & 127;
        int nc = u >> 5, rem = u & 31, nt = rem >> 3, g = rem & 7;
        g_w1p[k*128 + nc*32 + g*4 + nt] = f2tf32(W1[t]);
        int u2 = t >> 6, c = t & 63;
        int nc2 = c >> 5, rem2 = c & 31, nt2 = rem2 >> 3, g2 = rem2 & 7;
        g_w2p[u2*64 + nc2*32 + g2*4 + nt2] = f2tf32(W2[t]);
    }
}

// ---------------------------------------------------------------------------
// K1: node LN + Q/K/V projection (V also stored transposed).
// ---------------------------------------------------------------------------
__global__ void k_node_prep(const float* __restrict__ n,
                            const float* __restrict__ Wq,
                            const float* __restrict__ Wk,
                            const float* __restrict__ Wv,
                            const float* __restrict__ lng,
                            const float* __restrict__ lnb)
{
    int row = blockIdx.x;
    int o = threadIdx.x;
    __shared__ float sx[DD];
    __shared__ float sn1[DD];
    sx[o] = n[row*DD + o];
    __syncthreads();
    float s = 0.f;
    #pragma unroll
    for (int k = 0; k < DD; k++) s += sx[k];
    float m = s * (1.f/DD);
    float v = 0.f;
    #pragma unroll
    for (int k = 0; k < DD; k++) { float d = sx[k]-m; v += d*d; }
    v *= (1.f/DD);
    float rstd = rsqrtf(v + 1e-5f);
    float n1 = (sx[o]-m)*rstd*lng[o] + lnb[o];
    sn1[o] = n1;
    g_n1[row*DD + o] = n1;
    __syncthreads();
    float q = 0.f, kk = 0.f, vv = 0.f;
    #pragma unroll
    for (int k = 0; k < DD; k++) {
        float a = sn1[k];
        q  += a * Wq[k*DD + o];
        kk += a * Wk[k*DD + o];
        vv += a * Wv[k*DD + o];
    }
    g_q[row*DD + o] = q;
    g_k[row*DD + o] = kk;
    int b = row >> 9;
    int j = row & 511;
    int h = o >> 3;
    int d = o & 7;
    g_vt[((b*HH + h)*8 + d)*NN + j] = vv;
}

// ---------------------------------------------------------------------------
// K2: edge attention (byte-identical to the 628us R12/R14 version).
// ---------------------------------------------------------------------------
__global__ void __launch_bounds__(256, 1)
k_edge(const float* __restrict__ e,
       const float* __restrict__ We, const float* __restrict__ Wg,
       const float* __restrict__ lg1, const float* __restrict__ lb1)
{
    extern __shared__ float sm[];
    float* sElog  = sm + OFF_ELOG;
    float* sWeP   = sm + OFF_WEP;
    float* sWgP   = sm + OFF_WGP;
    float* sQ     = sm + OFF_Q;
    float* sSe    = sm + OFF_SE;
    float* sCe    = sm + OFF_CE;
    float* sSg    = sm + OFF_SG;
    float* sCg    = sm + OFF_CG;
    float* sCent  = sm + OFF_CENT;
    float* sWpart = sm + OFF_WPART;
    float* sE     = sm + OFF_ET;
    float* sK     = sm + OFF_KT;

    const int i    = blockIdx.x;
    const int b    = blockIdx.y;
    const int tid  = threadIdx.x;
    const int lane = tid & 31;
    const int warp = tid >> 5;
    const int rowbn = b*NN + i;

    const int r    = tid >> 1;
    const int half = tid & 1;
    const int k0w  = half * 32;

    for (int t = tid; t < 512; t += 256) {
        int k = t >> 3;
        float g = lg1[k];
        sWeP[t] = g * We[t];
        sWgP[t] = g * Wg[t];
    }
    if (tid < 64) sQ[tid] = g_q[rowbn*DD + tid];
    __syncthreads();
    if (tid < 8) {
        float se=0.f, ce=0.f, sg=0.f, cg=0.f;
        for (int k = 0; k < 64; k++) {
            float bb = lb1[k];
            se += sWeP[k*8 + tid];
            sg += sWgP[k*8 + tid];
            ce += bb * We[k*8 + tid];
            cg += bb * Wg[k*8 + tid];
        }
        sSe[tid]=se; sCe[tid]=ce; sSg[tid]=sg; sCg[tid]=cg;
    }

    const float scale = 0.35355339059327373f;
    float gacc[HH];
    #pragma unroll
    for (int h = 0; h < HH; h++) gacc[h] = 0.f;

    for (int ch = 0; ch < 4; ch++) {
        const int j0 = ch*128;
        __syncthreads();
        for (int t = tid; t < 2048; t += 256) {
            int row = t >> 4, q = t & 15;
            *(float4*)(sE + row*68 + q*4) =
                *(const float4*)(e + ((size_t)rowbn*NN + j0 + row)*DD + q*4);
            *(float4*)(sK + row*68 + q*4) =
                *(const float4*)(g_k + ((size_t)b*NN + j0 + row)*DD + q*4);
        }
        __syncthreads();

        float s = 0.f, sq = 0.f;
        float Eh[HH], Gh[HH];
        #pragma unroll
        for (int h = 0; h < HH; h++) { Eh[h]=0.f; Gh[h]=0.f; }
        float ac0=0.f, ac1=0.f, ac2=0.f, ac3=0.f;

        const float4* xp = (const float4*)(sE + r*68 + k0w);
        const float4* kp = (const float4*)(sK + r*68 + k0w);
        const float4* qp = (const float4*)(sQ + k0w);

        #pragma unroll
        for (int q = 0; q < 8; q++) {
            float4 xv = xp[q];
            float4 kv = kp[q];
            float4 qv = qp[q];
            s  += (xv.x + xv.y) + (xv.z + xv.w);
            sq += (xv.x*xv.x + xv.y*xv.y) + (xv.z*xv.z + xv.w*xv.w);
            float dot = qv.x*kv.x + qv.y*kv.y + qv.z*kv.z + qv.w*kv.w;
            if (q < 2)      ac0 += dot;
            else if (q < 4) ac1 += dot;
            else if (q < 6) ac2 += dot;
            else            ac3 += dot;
            float xs[4] = {xv.x, xv.y, xv.z, xv.w};
            #pragma unroll
            for (int c = 0; c < 4; c++) {
                int k = k0w + q*4 + c;
                float xk = xs[c];
                const float4* we = (const float4*)(sWeP + k*8);
                const float4* wg = (const float4*)(sWgP + k*8);
                float4 a0 = we[0], a1 = we[1];
                float4 c0 = wg[0], c1 = wg[1];
                Eh[0]+=xk*a0.x; Eh[1]+=xk*a0.y; Eh[2]+=xk*a0.z; Eh[3]+=xk*a0.w;
                Eh[4]+=xk*a1.x; Eh[5]+=xk*a1.y; Eh[6]+=xk*a1.z; Eh[7]+=xk*a1.w;
                Gh[0]+=xk*c0.x; Gh[1]+=xk*c0.y; Gh[2]+=xk*c0.z; Gh[3]+=xk*c0.w;
                Gh[4]+=xk*c1.x; Gh[5]+=xk*c1.y; Gh[6]+=xk*c1.z; Gh[7]+=xk*c1.w;
            }
        }

        s  += __shfl_xor_sync(0xffffffffu, s, 1);
        sq += __shfl_xor_sync(0xffffffffu, sq, 1);
        #pragma unroll
        for (int h = 0; h < HH; h++) {
            Eh[h] += __shfl_xor_sync(0xffffffffu, Eh[h], 1);
            Gh[h] += __shfl_xor_sync(0xffffffffu, Gh[h], 1);
        }
        float p0 = __shfl_xor_sync(0xffffffffu, ac0, 1);
        float p1 = __shfl_xor_sync(0xffffffffu, ac1, 1);
        float p2 = __shfl_xor_sync(0xffffffffu, ac2, 1);
        float p3 = __shfl_xor_sync(0xffffffffu, ac3, 1);
        float qk0 = half ? p0 : ac0;
        float qk1 = half ? p1 : ac1;
        float qk2 = half ? p2 : ac2;
        float qk3 = half ? p3 : ac3;
        float qk4 = half ? ac0 : p0;
        float qk5 = half ? ac1 : p1;
        float qk6 = half ? ac2 : p2;
        float qk7 = half ? ac3 : p3;

        float m = s * (1.f/64.f);
        float var = sq * (1.f/64.f) - m*m;
        float rstd = rsqrtf(var + 1e-5f);

        if (half == 0) {
            const int j = j0 + r;
            float qks[8] = {qk0,qk1,qk2,qk3,qk4,qk5,qk6,qk7};
            #pragma unroll
            for (int h = 0; h < HH; h++) {
                float E = rstd*(Eh[h] - m*sSe[h]) + sCe[h];
                float G = rstd*(Gh[h] - m*sSg[h]) + sCg[h];
                float a = fminf(fmaxf(qks[h]*scale, -5.f), 5.f);
                sElog[h*520 + j] = a + E;
                gacc[h] += 1.f/(1.f + expf(-G));
            }
        }
    }

    #pragma unroll
    for (int h = 0; h < HH; h++) {
        #pragma unroll
        for (int off = 16; off > 0; off >>= 1)
            gacc[h] += __shfl_xor_sync(0xffffffffu, gacc[h], off);
    }
    if (lane == 0) {
        #pragma unroll
        for (int h = 0; h < HH; h++) sWpart[warp*8 + h] = gacc[h];
    }
    __syncthreads();
    if (tid < 8) {
        float ssum = 0.f;
        #pragma unroll
        for (int w = 0; w < 8; w++) ssum += sWpart[w*8 + tid];
        sCent[tid] = log1pf(ssum);
    }
    __syncthreads();

    {
        const int h = warp;
        const float* el = sElog + h*520;
        const float* vt = g_vt + (size_t)(b*HH + h)*8*NN;
        float mmax = -1e30f;
        for (int j = lane; j < NN; j += 32) mmax = fmaxf(mmax, el[j]);
        #pragma unroll
        for (int off = 16; off > 0; off >>= 1)
            mmax = fmaxf(mmax, __shfl_xor_sync(0xffffffffu, mmax, off));

        float denom = 0.f;
        float p0=0,p1=0,p2=0,p3=0,p4=0,p5=0,p6=0,p7=0;
        for (int j = lane; j < NN; j += 32) {
            float t = expf(el[j] - mmax);
            denom += t;
            p0 += t*vt[0*NN + j];
            p1 += t*vt[1*NN + j];
            p2 += t*vt[2*NN + j];
            p3 += t*vt[3*NN + j];
            p4 += t*vt[4*NN + j];
            p5 += t*vt[5*NN + j];
            p6 += t*vt[6*NN + j];
            p7 += t*vt[7*NN + j];
        }
        #pragma unroll
        for (int off = 16; off > 0; off >>= 1) {
            denom += __shfl_xor_sync(0xffffffffu, denom, off);
            p0 += __shfl_xor_sync(0xffffffffu, p0, off);
            p1 += __shfl_xor_sync(0xffffffffu, p1, off);
            p2 += __shfl_xor_sync(0xffffffffu, p2, off);
            p3 += __shfl_xor_sync(0xffffffffu, p3, off);
            p4 += __shfl_xor_sync(0xffffffffu, p4, off);
            p5 += __shfl_xor_sync(0xffffffffu, p5, off);
            p6 += __shfl_xor_sync(0xffffffffu, p6, off);
            p7 += __shfl_xor_sync(0xffffffffu, p7, off);
        }
        if (lane == 0) {
            float c = sCent[h] / denom;
            float* dst = g_vc + rowbn*DD + h*8;
            dst[0]=p0*c; dst[1]=p1*c; dst[2]=p2*c; dst[3]=p3*c;
            dst[4]=p4*c; dst[5]=p5*c; dst[6]=p6*c; dst[7]=p7*c;
        }
    }

    __syncthreads();
    for (int t = tid; t < HH*NN; t += 256) {
        int h = t >> 9, j = t & 511;
        g_elog[(((size_t)b*HH + h)*NN + i)*NN + j] = sElog[h*520 + j];
    }
}

// ---------------------------------------------------------------------------
// K3 v2: fused edge finish + MLP. 128 threads, 64-edge tile, weights from
// gmem (permuted tf32). 57KB smem -> 3 CTAs/SM.
// ---------------------------------------------------------------------------
__global__ void __launch_bounds__(128, 1)
k_edge_finish_mlp(const float* __restrict__ e,
                  const float* __restrict__ WoE,
                  const float* __restrict__ lg1, const float* __restrict__ lb1,
                  const float* __restrict__ lg2, const float* __restrict__ lb2,
                  const float* __restrict__ b1, const float* __restrict__ b2,
                  float* __restrict__ e_out)
{
    extern __shared__ float sm[];
    float*    sA   = sm + KA_OFF;               // fp32 [64][68]
    uint32_t* sH   = (uint32_t*)(sm + KH_OFF);  // tf32 [64][132]
    float*    sB1  = sm + KB1_OFF;
    float*    sB2  = sm + KB2_OFF;
    float*    sWoe = sm + KWOE_OFF;
    float*    sEl  = sm + KEL_OFF;              // [8][64]
    float*    sG1  = sm + KG1_OFF;
    float*    sBe1 = sm + KBE1_OFF;
    float*    sG2  = sm + KG2_OFF;
    float*    sBe2 = sm + KBE2_OFF;

    const int tid  = threadIdx.x;
    const int lane = tid & 31;
    const int warp = tid >> 5;
    const int gid  = lane >> 2;
    const int tig  = lane & 3;

    const int bx = blockIdx.x;
    const int jc = bx & 7;          // 8 chunks of 64
    const int i  = bx >> 3;
    const int b  = blockIdx.y;
    const int rowbn = b*NN + i;
    const size_t gj0 = (size_t)rowbn*NN + jc*64;

    for (int t = tid; t < 512; t += 128) sWoe[t] = WoE[t];
    if (tid < 128) sB1[tid] = b1[tid];
    if (tid < 64) {
        sB2[tid]  = b2[tid];
        sG1[tid]  = lg1[tid]; sBe1[tid] = lb1[tid];
        sG2[tid]  = lg2[tid]; sBe2[tid] = lb2[tid];
    }
    for (int t = tid; t < 512; t += 128) {
        int h = t >> 6, jl = t & 63;
        sEl[h*64 + jl] = g_elog[(((size_t)b*HH + h)*NN + i)*NN + jc*64 + jl];
    }
    for (int t = tid; t < 64*16; t += 128) {
        int row = t >> 4, q = t & 15;
        float4 v = *(const float4*)(e + (gj0 + row)*DD + q*4);
        *(float4*)(sA + row*68 + q*4) = v;
    }
    __syncthreads();

    // phase A: e3 = LN2( LN1(x) + El @ WoE ) in sA  (r in [0,64))
    {
        const int r     = tid >> 1;
        const int halfc = tid & 1;
        const int c0    = halfc*32;

        float s = 0.f, sq = 0.f;
        #pragma unroll
        for (int c = 0; c < 32; c++) {
            float v = sA[r*68 + c0 + c];
            s += v; sq += v*v;
        }
        s  += __shfl_xor_sync(0xffffffffu, s, 1);
        sq += __shfl_xor_sync(0xffffffffu, sq, 1);
        float m = s*(1.f/64.f);
        float rstd = rsqrtf(sq*(1.f/64.f) - m*m + 1e-5f);

        float el0=sEl[r],     el1=sEl[64+r],  el2=sEl[128+r], el3=sEl[192+r];
        float el4=sEl[256+r], el5=sEl[320+r], el6=sEl[384+r], el7=sEl[448+r];

        float y[32];
        #pragma unroll
        for (int c = 0; c < 32; c++) {
            int k = c0 + c;
            float x = sA[r*68 + k];
            float a = (x - m)*rstd*sG1[k] + sBe1[k];
            a += el0*sWoe[k]       + el1*sWoe[64 + k]
               + el2*sWoe[128 + k] + el3*sWoe[192 + k]
               + el4*sWoe[256 + k] + el5*sWoe[320 + k]
               + el6*sWoe[384 + k] + el7*sWoe[448 + k];
            y[c] = a;
        }
        float s2 = 0.f, q2 = 0.f;
        #pragma unroll
        for (int c = 0; c < 32; c++) { s2 += y[c]; q2 += y[c]*y[c]; }
        s2 += __shfl_xor_sync(0xffffffffu, s2, 1);
        q2 += __shfl_xor_sync(0xffffffffu, q2, 1);
        float m2 = s2*(1.f/64.f);
        float rstd2 = rsqrtf(q2*(1.f/64.f) - m2*m2 + 1e-5f);
        #pragma unroll
        for (int c = 0; c < 32; c++) {
            int k = c0 + c;
            sA[r*68 + k] = (y[c] - m2)*rstd2*sG2[k] + sBe2[k];
        }
    }
    __syncthreads();

    // phase B: tf32 mma MLP, B-fragments from gmem (L2-hot broadcast)
    const int row0 = warp*16 + gid;     // warps 0..3 -> rows 0..63
    const int row1 = row0 + 8;

    uint32_t af0[8], af1[8], af2[8], af3[8];
    #pragma unroll
    for (int kt = 0; kt < 8; kt++) {
        int c0 = kt*8 + tig;
        af0[kt] = f2tf32(sA[row0*68 + c0]);
        af1[kt] = f2tf32(sA[row1*68 + c0]);
        af2[kt] = f2tf32(sA[row0*68 + c0 + 4]);
        af3[kt] = f2tf32(sA[row1*68 + c0 + 4]);
    }

    #pragma unroll
    for (int nc = 0; nc < 4; nc++) {
        float a00=0,a01=0,a02=0,a03=0;
        float a10=0,a11=0,a12=0,a13=0;
        float a20=0,a21=0,a22=0,a23=0;
        float a30=0,a31=0,a32=0,a33=0;
        #pragma unroll
        for (int kt = 0; kt < 8; kt++) {
            const uint4 bv0 = *(const uint4*)(g_w1p + (kt*8 + tig)*128 + nc*32 + gid*4);
            const uint4 bv1 = *(const uint4*)(g_w1p + (kt*8 + tig + 4)*128 + nc*32 + gid*4);
            mma_tf32(a00,a01,a02,a03, af0[kt],af1[kt],af2[kt],af3[kt], bv0.x,bv1.x);
            mma_tf32(a10,a11,a12,a13, af0[kt],af1[kt],af2[kt],af3[kt], bv0.y,bv1.y);
            mma_tf32(a20,a21,a22,a23, af0[kt],af1[kt],af2[kt],af3[kt], bv0.z,bv1.z);
            mma_tf32(a30,a31,a32,a33, af0[kt],af1[kt],af2[kt],af3[kt], bv0.w,bv1.w);
        }
        #pragma unroll
        for (int nt = 0; nt < 4; nt++) {
            float c0v, c1v, c2v, c3v;
            if (nt == 0)      { c0v=a00; c1v=a01; c2v=a02; c3v=a03; }
            else if (nt == 1) { c0v=a10; c1v=a11; c2v=a12; c3v=a13; }
            else if (nt == 2) { c0v=a20; c1v=a21; c2v=a22; c3v=a23; }
            else              { c0v=a30; c1v=a31; c2v=a32; c3v=a33; }
            int c = nc*32 + nt*8 + 2*tig;
            float bb0 = sB1[c], bb1 = sB1[c+1];
            sH[row0*132 + c    ] = f2tf32(fmaxf(c0v + bb0, 0.f));
            sH[row0*132 + c + 1] = f2tf32(fmaxf(c1v + bb1, 0.f));
            sH[row1*132 + c    ] = f2tf32(fmaxf(c2v + bb0, 0.f));
            sH[row1*132 + c + 1] = f2tf32(fmaxf(c3v + bb1, 0.f));
        }
    }
    __syncwarp();

    #pragma unroll
    for (int nc = 0; nc < 2; nc++) {
        float a00=0,a01=0,a02=0,a03=0;
        float a10=0,a11=0,a12=0,a13=0;
        float a20=0,a21=0,a22=0,a23=0;
        float a30=0,a31=0,a32=0,a33=0;
        #pragma unroll
        for (int kt = 0; kt < 16; kt++) {
            int c0 = kt*8 + tig;
            uint32_t h0 = sH[row0*132 + c0];
            uint32_t h1 = sH[row1*132 + c0];
            uint32_t h2 = sH[row0*132 + c0 + 4];
            uint32_t h3 = sH[row1*132 + c0 + 4];
            const uint4 bv0 = *(const uint4*)(g_w2p + c0*64 + nc*32 + gid*4);
            const uint4 bv1 = *(const uint4*)(g_w2p + (c0 + 4)*64 + nc*32 + gid*4);
            mma_tf32(a00,a01,a02,a03, h0,h1,h2,h3, bv0.x,bv1.x);
            mma_tf32(a10,a11,a12,a13, h0,h1,h2,h3, bv0.y,bv1.y);
            mma_tf32(a20,a21,a22,a23, h0,h1,h2,h3, bv0.z,bv1.z);
            mma_tf32(a30,a31,a32,a33, h0,h1,h2,h3, bv0.w,bv1.w);
        }
        #pragma unroll
        for (int nt = 0; nt < 4; nt++) {
            float c0v, c1v, c2v, c3v;
            if (nt == 0)      { c0v=a00; c1v=a01; c2v=a02; c3v=a03; }
            else if (nt == 1) { c0v=a10; c1v=a11; c2v=a12; c3v=a13; }
            else if (nt == 2) { c0v=a20; c1v=a21; c2v=a22; c3v=a23; }
            else              { c0v=a30; c1v=a31; c2v=a32; c3v=a33; }
            int c = nc*32 + nt*8 + 2*tig;
            float b20v = sB2[c], b21v = sB2[c+1];
            float r00 = sA[row0*68 + c    ] + fmaxf(c0v + b20v, 0.f);
            float r01 = sA[row0*68 + c + 1] + fmaxf(c1v + b21v, 0.f);
            float r10 = sA[row1*68 + c    ] + fmaxf(c2v + b20v, 0.f);
            float r11 = sA[row1*68 + c + 1] + fmaxf(c3v + b21v, 0.f);
            *(float2*)(e_out + (gj0 + row0)*DD + c) = make_float2(r00, r01);
            *(float2*)(e_out + (gj0 + row1)*DD + c) = make_float2(r10, r11);
        }
    }
}

// ---------------------------------------------------------------------------
// K4: node finish.
// ---------------------------------------------------------------------------
__global__ void k_node_finish(const float* __restrict__ Wo_n,
                              const float* __restrict__ lng,
                              const float* __restrict__ lnb,
                              const float* __restrict__ W1,
                              const float* __restrict__ Bi1,
                              const float* __restrict__ W2,
                              const float* __restrict__ Bi2,
                              float* __restrict__ n_out)
{
    int row = blockIdx.x;
    int o = threadIdx.x;
    __shared__ float svc[DD];
    __shared__ float sn2[DD];
    __shared__ float sn3[DD];
    __shared__ float sh[DHH];
    svc[o] = g_vc[row*DD + o];
    __syncthreads();
    float acc = 0.f;
    #pragma unroll
    for (int k = 0; k < DD; k++) acc += svc[k]*Wo_n[k*DD + o];
    float n2 = g_n1[row*DD + o] + acc;
    sn2[o] = n2;
    __syncthreads();
    float s = 0.f;
    #pragma unroll
    for (int k = 0; k < DD; k++) s += sn2[k];
    float m = s*(1.f/DD);
    float v = 0.f;
    #pragma unroll
    for (int k = 0; k < DD; k++) { float d = sn2[k]-m; v += d*d; }
    v *= (1.f/DD);
    float rstd = rsqrtf(v + 1e-5f);
    float n3 = (n2-m)*rstd*lng[o] + lnb[o];
    sn3[o] = n3;
    __syncthreads();
    #pragma unroll
    for (int uu = 0; uu < 2; uu++) {
        int u = o + uu*64;
        float h = Bi1[u];
        #pragma unroll
        for (int k = 0; k < DD; k++) h += sn3[k]*W1[k*DHH + u];
        sh[u] = fmaxf(h, 0.f);
    }
    __syncthreads();
    float oacc = Bi2[o];
    #pragma unroll
    for (int u = 0; u < DHH; u++) oacc += sh[u]*W2[u*DD + o];
    n_out[row*DD + o] = n3 + fmaxf(oacc, 0.f);
}

extern "C" void kernel_launch(void* const* d_in, const int* in_sizes, int n_in,
                              void* d_out, int out_size)
{
    const float* n       = (const float*)d_in[0];
    const float* e       = (const float*)d_in[1];
    const float* Wq      = (const float*)d_in[2];
    const float* Wk      = (const float*)d_in[3];
    const float* Wv      = (const float*)d_in[4];
    const float* Wo_n    = (const float*)d_in[5];
    const float* We      = (const float*)d_in[6];
    const float* Wg      = (const float*)d_in[7];
    const float* Wo_e    = (const float*)d_in[8];
    const float* ln_n1_g = (const float*)d_in[9];
    const float* ln_n1_b = (const float*)d_in[10];
    const float* ln_e1_g = (const float*)d_in[11];
    const float* ln_e1_b = (const float*)d_in[12];
    const float* ln_n2_g = (const float*)d_in[13];
    const float* ln_n2_b = (const float*)d_in[14];
    const float* ln_e2_g = (const float*)d_in[15];
    const float* ln_e2_b = (const float*)d_in[16];
    const float* mn_w1   = (const float*)d_in[17];
    const float* mn_b1   = (const float*)d_in[18];
    const float* mn_w2   = (const float*)d_in[19];
    const float* mn_b2   = (const float*)d_in[20];
    const float* me_w1   = (const float*)d_in[21];
    const float* me_b1   = (const float*)d_in[22];
    const float* me_w2   = (const float*)d_in[23];
    const float* me_b2   = (const float*)d_in[24];

    float* out   = (float*)d_out;
    float* n_out = out;
    float* e_out = out + BB*NN*DD;

    cudaFuncSetAttribute(k_edge, cudaFuncAttributeMaxDynamicSharedMemorySize, EDGE_SMEM_BYTES);
    cudaFuncSetAttribute(k_edge_finish_mlp, cudaFuncAttributeMaxDynamicSharedMemorySize, K3_SMEM_BYTES);

    k_w_prep<<<32, 256>>>(me_w1, me_w2);
    k_node_prep<<<BB*NN, 64>>>(n, Wq, Wk, Wv, ln_n1_g, ln_n1_b);

    dim3 grid2(NN, BB);
    k_edge<<<grid2, 256, EDGE_SMEM_BYTES>>>(e, We, Wg, ln_e1_g, ln_e1_b);

    dim3 grid3(8*NN, BB);
    k_edge_finish_mlp<<<grid3, 128, K3_SMEM_BYTES>>>(e, Wo_e,
                                                     ln_e1_g, ln_e1_b,
                                                     ln_e2_g, ln_e2_b,
                                                     me_b1, me_b2,
                                                     e_out);

    k_node_finish<<<BB*NN, 64>>>(Wo_n, ln_n2_g, ln_n2_b,
                                 mn_w1, mn_b1, mn_w2, mn_b2, n_out);
}

// round 16
// speedup vs baseline: 1.0898x; 1.0898x over previous
#include <cuda_runtime.h>
#include <math.h>
#include <stdint.h>

#define BB 2
#define NN 512
#define DD 64
#define HH 8
#define DHH 128

// ----------------- k_edge smem layout (floats) -----------------
#define OFF_ELOG   0        // 8*520 = 4160
#define OFF_WEP    4160     // 512
#define OFF_WGP    4672     // 512
#define OFF_Q      5184     // 64
#define OFF_SE     5248     // 8
#define OFF_CE     5256     // 8
#define OFF_SG     5264     // 8
#define OFF_CG     5272     // 8
#define OFF_CENT   5280     // 8
#define OFF_WPART  5288     // 64
#define OFF_ET     5352     // 128 x 68
#define OFF_KT     14056    // 128 x 68
#define EDGE_SMEM_FLOATS 22760
#define EDGE_SMEM_BYTES  (EDGE_SMEM_FLOATS*4)   // 91040 B

// ----------------- K3 v3 (128 thr, 64-edge tile) smem (floats) -----------
#define KA_OFF    0          // sA 64 x 68 fp32   (4352)
#define KH_OFF    4352       // sH 64 x 132 tf32  (8448)
#define KB1_OFF   12800      // 128
#define KB2_OFF   12928      // 64
#define KWOE_OFF  12992      // 512
#define KEL_OFF   13504      // 512 (Elog slice [8][64])
#define KG1_OFF   14016      // 64
#define KBE1_OFF  14080      // 64
#define KG2_OFF   14144      // 64
#define KBE2_OFF  14208      // 64
#define K3_SMEM_FLOATS 14272
#define K3_SMEM_BYTES  (K3_SMEM_FLOATS*4)   // 57088 B

__device__ __align__(16) float g_n1[BB*NN*DD];
__device__ __align__(16) float g_q [BB*NN*DD];
__device__ __align__(16) float g_k [BB*NN*DD];
__device__ __align__(16) float g_vt[BB*HH*8*NN];
__device__ __align__(16) float g_vc[BB*NN*DD];
__device__ __align__(16) float g_elog[(size_t)BB*HH*NN*NN];
__device__ __align__(16) uint32_t g_w1p[64*DHH];   // permuted tf32 W1
__device__ __align__(16) uint32_t g_w2p[DHH*64];   // permuted tf32 W2

__device__ __forceinline__ uint32_t f2tf32(float x) {
    uint32_t r;
    asm("cvt.rna.tf32.f32 %0, %1;" : "=r"(r) : "f"(x));
    return r;
}

__device__ __forceinline__ void mma_tf32(float& c0, float& c1, float& c2, float& c3,
                                         uint32_t a0, uint32_t a1,
                                         uint32_t a2, uint32_t a3,
                                         uint32_t b0, uint32_t b1) {
    asm volatile(
        "mma.sync.aligned.m16n8k8.row.col.f32.tf32.tf32.f32 "
        "{%0,%1,%2,%3},{%4,%5,%6,%7},{%8,%9},{%0,%1,%2,%3};"
        : "+f"(c0), "+f"(c1), "+f"(c2), "+f"(c3)
        : "r"(a0), "r"(a1), "r"(a2), "r"(a3), "r"(b0), "r"(b1));
}

// ---------------------------------------------------------------------------
// K0: convert + permute MLP weights to tf32 in gmem.
// ---------------------------------------------------------------------------
__global__ void k_w_prep(const float* __restrict__ W1, const float* __restrict__ W2)
{
    int t = blockIdx.x*256 + threadIdx.x;
    if (t < 64*DHH) {
        int k = t >> 7, u = t & 127;
        int nc = u >> 5, rem = u & 31, nt = rem >> 3, g = rem & 7;
        g_w1p[k*128 + nc*32 + g*4 + nt] = f2tf32(W1[t]);
        int u2 = t >> 6, c = t & 63;
        int nc2 = c >> 5, rem2 = c & 31, nt2 = rem2 >> 3, g2 = rem2 & 7;
        g_w2p[u2*64 + nc2*32 + g2*4 + nt2] = f2tf32(W2[t]);
    }
}

// ---------------------------------------------------------------------------
// K1: node LN + Q/K/V projection (V also stored transposed).
// ---------------------------------------------------------------------------
__global__ void k_node_prep(const float* __restrict__ n,
                            const float* __restrict__ Wq,
                            const float* __restrict__ Wk,
                            const float* __restrict__ Wv,
                            const float* __restrict__ lng,
                            const float* __restrict__ lnb)
{
    int row = blockIdx.x;
    int o = threadIdx.x;
    __shared__ float sx[DD];
    __shared__ float sn1[DD];
    sx[o] = n[row*DD + o];
    __syncthreads();
    float s = 0.f;
    #pragma unroll
    for (int k = 0; k < DD; k++) s += sx[k];
    float m = s * (1.f/DD);
    float v = 0.f;
    #pragma unroll
    for (int k = 0; k < DD; k++) { float d = sx[k]-m; v += d*d; }
    v *= (1.f/DD);
    float rstd = rsqrtf(v + 1e-5f);
    float n1 = (sx[o]-m)*rstd*lng[o] + lnb[o];
    sn1[o] = n1;
    g_n1[row*DD + o] = n1;
    __syncthreads();
    float q = 0.f, kk = 0.f, vv = 0.f;
    #pragma unroll
    for (int k = 0; k < DD; k++) {
        float a = sn1[k];
        q  += a * Wq[k*DD + o];
        kk += a * Wk[k*DD + o];
        vv += a * Wv[k*DD + o];
    }
    g_q[row*DD + o] = q;
    g_k[row*DD + o] = kk;
    int b = row >> 9;
    int j = row & 511;
    int h = o >> 3;
    int d = o & 7;
    g_vt[((b*HH + h)*8 + d)*NN + j] = vv;
}

// ---------------------------------------------------------------------------
// K2: edge attention (byte-identical to the 628us build).
// ---------------------------------------------------------------------------
__global__ void __launch_bounds__(256, 1)
k_edge(const float* __restrict__ e,
       const float* __restrict__ We, const float* __restrict__ Wg,
       const float* __restrict__ lg1, const float* __restrict__ lb1)
{
    extern __shared__ float sm[];
    float* sElog  = sm + OFF_ELOG;
    float* sWeP   = sm + OFF_WEP;
    float* sWgP   = sm + OFF_WGP;
    float* sQ     = sm + OFF_Q;
    float* sSe    = sm + OFF_SE;
    float* sCe    = sm + OFF_CE;
    float* sSg    = sm + OFF_SG;
    float* sCg    = sm + OFF_CG;
    float* sCent  = sm + OFF_CENT;
    float* sWpart = sm + OFF_WPART;
    float* sE     = sm + OFF_ET;
    float* sK     = sm + OFF_KT;

    const int i    = blockIdx.x;
    const int b    = blockIdx.y;
    const int tid  = threadIdx.x;
    const int lane = tid & 31;
    const int warp = tid >> 5;
    const int rowbn = b*NN + i;

    const int r    = tid >> 1;
    const int half = tid & 1;
    const int k0w  = half * 32;

    for (int t = tid; t < 512; t += 256) {
        int k = t >> 3;
        float g = lg1[k];
        sWeP[t] = g * We[t];
        sWgP[t] = g * Wg[t];
    }
    if (tid < 64) sQ[tid] = g_q[rowbn*DD + tid];
    __syncthreads();
    if (tid < 8) {
        float se=0.f, ce=0.f, sg=0.f, cg=0.f;
        for (int k = 0; k < 64; k++) {
            float bb = lb1[k];
            se += sWeP[k*8 + tid];
            sg += sWgP[k*8 + tid];
            ce += bb * We[k*8 + tid];
            cg += bb * Wg[k*8 + tid];
        }
        sSe[tid]=se; sCe[tid]=ce; sSg[tid]=sg; sCg[tid]=cg;
    }

    const float scale = 0.35355339059327373f;
    float gacc[HH];
    #pragma unroll
    for (int h = 0; h < HH; h++) gacc[h] = 0.f;

    for (int ch = 0; ch < 4; ch++) {
        const int j0 = ch*128;
        __syncthreads();
        for (int t = tid; t < 2048; t += 256) {
            int row = t >> 4, q = t & 15;
            *(float4*)(sE + row*68 + q*4) =
                *(const float4*)(e + ((size_t)rowbn*NN + j0 + row)*DD + q*4);
            *(float4*)(sK + row*68 + q*4) =
                *(const float4*)(g_k + ((size_t)b*NN + j0 + row)*DD + q*4);
        }
        __syncthreads();

        float s = 0.f, sq = 0.f;
        float Eh[HH], Gh[HH];
        #pragma unroll
        for (int h = 0; h < HH; h++) { Eh[h]=0.f; Gh[h]=0.f; }
        float ac0=0.f, ac1=0.f, ac2=0.f, ac3=0.f;

        const float4* xp = (const float4*)(sE + r*68 + k0w);
        const float4* kp = (const float4*)(sK + r*68 + k0w);
        const float4* qp = (const float4*)(sQ + k0w);

        #pragma unroll
        for (int q = 0; q < 8; q++) {
            float4 xv = xp[q];
            float4 kv = kp[q];
            float4 qv = qp[q];
            s  += (xv.x + xv.y) + (xv.z + xv.w);
            sq += (xv.x*xv.x + xv.y*xv.y) + (xv.z*xv.z + xv.w*xv.w);
            float dot = qv.x*kv.x + qv.y*kv.y + qv.z*kv.z + qv.w*kv.w;
            if (q < 2)      ac0 += dot;
            else if (q < 4) ac1 += dot;
            else if (q < 6) ac2 += dot;
            else            ac3 += dot;
            float xs[4] = {xv.x, xv.y, xv.z, xv.w};
            #pragma unroll
            for (int c = 0; c < 4; c++) {
                int k = k0w + q*4 + c;
                float xk = xs[c];
                const float4* we = (const float4*)(sWeP + k*8);
                const float4* wg = (const float4*)(sWgP + k*8);
                float4 a0 = we[0], a1 = we[1];
                float4 c0 = wg[0], c1 = wg[1];
                Eh[0]+=xk*a0.x; Eh[1]+=xk*a0.y; Eh[2]+=xk*a0.z; Eh[3]+=xk*a0.w;
                Eh[4]+=xk*a1.x; Eh[5]+=xk*a1.y; Eh[6]+=xk*a1.z; Eh[7]+=xk*a1.w;
                Gh[0]+=xk*c0.x; Gh[1]+=xk*c0.y; Gh[2]+=xk*c0.z; Gh[3]+=xk*c0.w;
                Gh[4]+=xk*c1.x; Gh[5]+=xk*c1.y; Gh[6]+=xk*c1.z; Gh[7]+=xk*c1.w;
            }
        }

        s  += __shfl_xor_sync(0xffffffffu, s, 1);
        sq += __shfl_xor_sync(0xffffffffu, sq, 1);
        #pragma unroll
        for (int h = 0; h < HH; h++) {
            Eh[h] += __shfl_xor_sync(0xffffffffu, Eh[h], 1);
            Gh[h] += __shfl_xor_sync(0xffffffffu, Gh[h], 1);
        }
        float p0 = __shfl_xor_sync(0xffffffffu, ac0, 1);
        float p1 = __shfl_xor_sync(0xffffffffu, ac1, 1);
        float p2 = __shfl_xor_sync(0xffffffffu, ac2, 1);
        float p3 = __shfl_xor_sync(0xffffffffu, ac3, 1);
        float qk0 = half ? p0 : ac0;
        float qk1 = half ? p1 : ac1;
        float qk2 = half ? p2 : ac2;
        float qk3 = half ? p3 : ac3;
        float qk4 = half ? ac0 : p0;
        float qk5 = half ? ac1 : p1;
        float qk6 = half ? ac2 : p2;
        float qk7 = half ? ac3 : p3;

        float m = s * (1.f/64.f);
        float var = sq * (1.f/64.f) - m*m;
        float rstd = rsqrtf(var + 1e-5f);

        if (half == 0) {
            const int j = j0 + r;
            float qks[8] = {qk0,qk1,qk2,qk3,qk4,qk5,qk6,qk7};
            #pragma unroll
            for (int h = 0; h < HH; h++) {
                float E = rstd*(Eh[h] - m*sSe[h]) + sCe[h];
                float G = rstd*(Gh[h] - m*sSg[h]) + sCg[h];
                float a = fminf(fmaxf(qks[h]*scale, -5.f), 5.f);
                sElog[h*520 + j] = a + E;
                gacc[h] += 1.f/(1.f + expf(-G));
            }
        }
    }

    #pragma unroll
    for (int h = 0; h < HH; h++) {
        #pragma unroll
        for (int off = 16; off > 0; off >>= 1)
            gacc[h] += __shfl_xor_sync(0xffffffffu, gacc[h], off);
    }
    if (lane == 0) {
        #pragma unroll
        for (int h = 0; h < HH; h++) sWpart[warp*8 + h] = gacc[h];
    }
    __syncthreads();
    if (tid < 8) {
        float ssum = 0.f;
        #pragma unroll
        for (int w = 0; w < 8; w++) ssum += sWpart[w*8 + tid];
        sCent[tid] = log1pf(ssum);
    }
    __syncthreads();

    {
        const int h = warp;
        const float* el = sElog + h*520;
        const float* vt = g_vt + (size_t)(b*HH + h)*8*NN;
        float mmax = -1e30f;
        for (int j = lane; j < NN; j += 32) mmax = fmaxf(mmax, el[j]);
        #pragma unroll
        for (int off = 16; off > 0; off >>= 1)
            mmax = fmaxf(mmax, __shfl_xor_sync(0xffffffffu, mmax, off));

        float denom = 0.f;
        float p0=0,p1=0,p2=0,p3=0,p4=0,p5=0,p6=0,p7=0;
        for (int j = lane; j < NN; j += 32) {
            float t = expf(el[j] - mmax);
            denom += t;
            p0 += t*vt[0*NN + j];
            p1 += t*vt[1*NN + j];
            p2 += t*vt[2*NN + j];
            p3 += t*vt[3*NN + j];
            p4 += t*vt[4*NN + j];
            p5 += t*vt[5*NN + j];
            p6 += t*vt[6*NN + j];
            p7 += t*vt[7*NN + j];
        }
        #pragma unroll
        for (int off = 16; off > 0; off >>= 1) {
            denom += __shfl_xor_sync(0xffffffffu, denom, off);
            p0 += __shfl_xor_sync(0xffffffffu, p0, off);
            p1 += __shfl_xor_sync(0xffffffffu, p1, off);
            p2 += __shfl_xor_sync(0xffffffffu, p2, off);
            p3 += __shfl_xor_sync(0xffffffffu, p3, off);
            p4 += __shfl_xor_sync(0xffffffffu, p4, off);
            p5 += __shfl_xor_sync(0xffffffffu, p5, off);
            p6 += __shfl_xor_sync(0xffffffffu, p6, off);
            p7 += __shfl_xor_sync(0xffffffffu, p7, off);
        }
        if (lane == 0) {
            float c = sCent[h] / denom;
            float* dst = g_vc + rowbn*DD + h*8;
            dst[0]=p0*c; dst[1]=p1*c; dst[2]=p2*c; dst[3]=p3*c;
            dst[4]=p4*c; dst[5]=p5*c; dst[6]=p6*c; dst[7]=p7*c;
        }
    }

    __syncthreads();
    for (int t = tid; t < HH*NN; t += 256) {
        int h = t >> 9, j = t & 511;
        g_elog[(((size_t)b*HH + h)*NN + i)*NN + j] = sElog[h*520 + j];
    }
}

// ---------------------------------------------------------------------------
// K3 v3: fused edge finish + MLP, register-lean (no af/y arrays).
// 128 threads, 64-edge tile, gmem tf32 weights, 57KB smem.
// ---------------------------------------------------------------------------
__global__ void __launch_bounds__(128, 1)
k_edge_finish_mlp(const float* __restrict__ e,
                  const float* __restrict__ WoE,
                  const float* __restrict__ lg1, const float* __restrict__ lb1,
                  const float* __restrict__ lg2, const float* __restrict__ lb2,
                  const float* __restrict__ b1, const float* __restrict__ b2,
                  float* __restrict__ e_out)
{
    extern __shared__ float sm[];
    float*    sA   = sm + KA_OFF;               // fp32 [64][68]
    uint32_t* sH   = (uint32_t*)(sm + KH_OFF);  // tf32 [64][132]
    float*    sB1  = sm + KB1_OFF;
    float*    sB2  = sm + KB2_OFF;
    float*    sWoe = sm + KWOE_OFF;
    float*    sEl  = sm + KEL_OFF;              // [8][64]
    float*    sG1  = sm + KG1_OFF;
    float*    sBe1 = sm + KBE1_OFF;
    float*    sG2  = sm + KG2_OFF;
    float*    sBe2 = sm + KBE2_OFF;

    const int tid  = threadIdx.x;
    const int lane = tid & 31;
    const int warp = tid >> 5;
    const int gid  = lane >> 2;
    const int tig  = lane & 3;

    const int bx = blockIdx.x;
    const int jc = bx & 7;
    const int i  = bx >> 3;
    const int b  = blockIdx.y;
    const int rowbn = b*NN + i;
    const size_t gj0 = (size_t)rowbn*NN + jc*64;

    for (int t = tid; t < 512; t += 128) sWoe[t] = WoE[t];
    if (tid < 128) sB1[tid] = b1[tid];
    if (tid < 64) {
        sB2[tid]  = b2[tid];
        sG1[tid]  = lg1[tid]; sBe1[tid] = lb1[tid];
        sG2[tid]  = lg2[tid]; sBe2[tid] = lb2[tid];
    }
    for (int t = tid; t < 512; t += 128) {
        int h = t >> 6, jl = t & 63;
        sEl[h*64 + jl] = g_elog[(((size_t)b*HH + h)*NN + i)*NN + jc*64 + jl];
    }
    for (int t = tid; t < 64*16; t += 128) {
        int row = t >> 4, q = t & 15;
        float4 v = *(const float4*)(e + (gj0 + row)*DD + q*4);
        *(float4*)(sA + row*68 + q*4) = v;
    }
    __syncthreads();

    // phase A: y = LN1(x) + El@WoE written in place, then LN2 in place
    {
        const int r     = tid >> 1;
        const int halfc = tid & 1;
        const int c0    = halfc*32;

        float s = 0.f, sq = 0.f;
        #pragma unroll
        for (int c = 0; c < 32; c++) {
            float v = sA[r*68 + c0 + c];
            s += v; sq += v*v;
        }
        s  += __shfl_xor_sync(0xffffffffu, s, 1);
        sq += __shfl_xor_sync(0xffffffffu, sq, 1);
        float m = s*(1.f/64.f);
        float rstd = rsqrtf(sq*(1.f/64.f) - m*m + 1e-5f);

        float el0=sEl[r],     el1=sEl[64+r],  el2=sEl[128+r], el3=sEl[192+r];
        float el4=sEl[256+r], el5=sEl[320+r], el6=sEl[384+r], el7=sEl[448+r];

        float s2 = 0.f, q2 = 0.f;
        #pragma unroll
        for (int c = 0; c < 32; c++) {
            int k = c0 + c;
            float x = sA[r*68 + k];
            float a = (x - m)*rstd*sG1[k] + sBe1[k];
            a += el0*sWoe[k]       + el1*sWoe[64 + k]
               + el2*sWoe[128 + k] + el3*sWoe[192 + k]
               + el4*sWoe[256 + k] + el5*sWoe[320 + k]
               + el6*sWoe[384 + k] + el7*sWoe[448 + k];
            s2 += a; q2 += a*a;
            sA[r*68 + k] = a;                 // y in place (x dead after this)
        }
        s2 += __shfl_xor_sync(0xffffffffu, s2, 1);
        q2 += __shfl_xor_sync(0xffffffffu, q2, 1);
        float m2 = s2*(1.f/64.f);
        float rstd2 = rsqrtf(q2*(1.f/64.f) - m2*m2 + 1e-5f);
        __syncwarp();
        #pragma unroll
        for (int c = 0; c < 32; c++) {
            int k = c0 + c;
            float y = sA[r*68 + k];
            sA[r*68 + k] = (y - m2)*rstd2*sG2[k] + sBe2[k];
        }
    }
    __syncthreads();

    // phase B: tf32 mma MLP (A-fragments reloaded per chunk: low reg pressure)
    const int row0 = warp*16 + gid;
    const int row1 = row0 + 8;

    #pragma unroll
    for (int nc = 0; nc < 4; nc++) {
        float a00=0,a01=0,a02=0,a03=0;
        float a10=0,a11=0,a12=0,a13=0;
        float a20=0,a21=0,a22=0,a23=0;
        float a30=0,a31=0,a32=0,a33=0;
        #pragma unroll
        for (int kt = 0; kt < 8; kt++) {
            int c0 = kt*8 + tig;
            uint32_t f0 = f2tf32(sA[row0*68 + c0]);
            uint32_t f1 = f2tf32(sA[row1*68 + c0]);
            uint32_t f2 = f2tf32(sA[row0*68 + c0 + 4]);
            uint32_t f3 = f2tf32(sA[row1*68 + c0 + 4]);
            const uint4 bv0 = *(const uint4*)(g_w1p + c0*128 + nc*32 + gid*4);
            const uint4 bv1 = *(const uint4*)(g_w1p + (c0 + 4)*128 + nc*32 + gid*4);
            mma_tf32(a00,a01,a02,a03, f0,f1,f2,f3, bv0.x,bv1.x);
            mma_tf32(a10,a11,a12,a13, f0,f1,f2,f3, bv0.y,bv1.y);
            mma_tf32(a20,a21,a22,a23, f0,f1,f2,f3, bv0.z,bv1.z);
            mma_tf32(a30,a31,a32,a33, f0,f1,f2,f3, bv0.w,bv1.w);
        }
        #pragma unroll
        for (int nt = 0; nt < 4; nt++) {
            float c0v, c1v, c2v, c3v;
            if (nt == 0)      { c0v=a00; c1v=a01; c2v=a02; c3v=a03; }
            else if (nt == 1) { c0v=a10; c1v=a11; c2v=a12; c3v=a13; }
            else if (nt == 2) { c0v=a20; c1v=a21; c2v=a22; c3v=a23; }
            else              { c0v=a30; c1v=a31; c2v=a32; c3v=a33; }
            int c = nc*32 + nt*8 + 2*tig;
            float bb0 = sB1[c], bb1 = sB1[c+1];
            sH[row0*132 + c    ] = f2tf32(fmaxf(c0v + bb0, 0.f));
            sH[row0*132 + c + 1] = f2tf32(fmaxf(c1v + bb1, 0.f));
            sH[row1*132 + c    ] = f2tf32(fmaxf(c2v + bb0, 0.f));
            sH[row1*132 + c + 1] = f2tf32(fmaxf(c3v + bb1, 0.f));
        }
    }
    __syncwarp();

    #pragma unroll
    for (int nc = 0; nc < 2; nc++) {
        float a00=0,a01=0,a02=0,a03=0;
        float a10=0,a11=0,a12=0,a13=0;
        float a20=0,a21=0,a22=0,a23=0;
        float a30=0,a31=0,a32=0,a33=0;
        #pragma unroll
        for (int kt = 0; kt < 16; kt++) {
            int c0 = kt*8 + tig;
            uint32_t h0 = sH[row0*132 + c0];
            uint32_t h1 = sH[row1*132 + c0];
            uint32_t h2 = sH[row0*132 + c0 + 4];
            uint32_t h3 = sH[row1*132 + c0 + 4];
            const uint4 bv0 = *(const uint4*)(g_w2p + c0*64 + nc*32 + gid*4);
            const uint4 bv1 = *(const uint4*)(g_w2p + (c0 + 4)*64 + nc*32 + gid*4);
            mma_tf32(a00,a01,a02,a03, h0,h1,h2,h3, bv0.x,bv1.x);
            mma_tf32(a10,a11,a12,a13, h0,h1,h2,h3, bv0.y,bv1.y);
            mma_tf32(a20,a21,a22,a23, h0,h1,h2,h3, bv0.z,bv1.z);
            mma_tf32(a30,a31,a32,a33, h0,h1,h2,h3, bv0.w,bv1.w);
        }
        #pragma unroll
        for (int nt = 0; nt < 4; nt++) {
            float c0v, c1v, c2v, c3v;
            if (nt == 0)      { c0v=a00; c1v=a01; c2v=a02; c3v=a03; }
            else if (nt == 1) { c0v=a10; c1v=a11; c2v=a12; c3v=a13; }
            else if (nt == 2) { c0v=a20; c1v=a21; c2v=a22; c3v=a23; }
            else              { c0v=a30; c1v=a31; c2v=a32; c3v=a33; }
            int c = nc*32 + nt*8 + 2*tig;
            float b20v = sB2[c], b21v = sB2[c+1];
            float r00 = sA[row0*68 + c    ] + fmaxf(c0v + b20v, 0.f);
            float r01 = sA[row0*68 + c + 1] + fmaxf(c1v + b21v, 0.f);
            float r10 = sA[row1*68 + c    ] + fmaxf(c2v + b20v, 0.f);
            float r11 = sA[row1*68 + c + 1] + fmaxf(c3v + b21v, 0.f);
            *(float2*)(e_out + (gj0 + row0)*DD + c) = make_float2(r00, r01);
            *(float2*)(e_out + (gj0 + row1)*DD + c) = make_float2(r10, r11);
        }
    }
}

// ---------------------------------------------------------------------------
// K4: node finish.
// ---------------------------------------------------------------------------
__global__ void k_node_finish(const float* __restrict__ Wo_n,
                              const float* __restrict__ lng,
                              const float* __restrict__ lnb,
                              const float* __restrict__ W1,
                              const float* __restrict__ Bi1,
                              const float* __restrict__ W2,
                              const float* __restrict__ Bi2,
                              float* __restrict__ n_out)
{
    int row = blockIdx.x;
    int o = threadIdx.x;
    __shared__ float svc[DD];
    __shared__ float sn2[DD];
    __shared__ float sn3[DD];
    __shared__ float sh[DHH];
    svc[o] = g_vc[row*DD + o];
    __syncthreads();
    float acc = 0.f;
    #pragma unroll
    for (int k = 0; k < DD; k++) acc += svc[k]*Wo_n[k*DD + o];
    float n2 = g_n1[row*DD + o] + acc;
    sn2[o] = n2;
    __syncthreads();
    float s = 0.f;
    #pragma unroll
    for (int k = 0; k < DD; k++) s += sn2[k];
    float m = s*(1.f/DD);
    float v = 0.f;
    #pragma unroll
    for (int k = 0; k < DD; k++) { float d = sn2[k]-m; v += d*d; }
    v *= (1.f/DD);
    float rstd = rsqrtf(v + 1e-5f);
    float n3 = (n2-m)*rstd*lng[o] + lnb[o];
    sn3[o] = n3;
    __syncthreads();
    #pragma unroll
    for (int uu = 0; uu < 2; uu++) {
        int u = o + uu*64;
        float h = Bi1[u];
        #pragma unroll
        for (int k = 0; k < DD; k++) h += sn3[k]*W1[k*DHH + u];
        sh[u] = fmaxf(h, 0.f);
    }
    __syncthreads();
    float oacc = Bi2[o];
    #pragma unroll
    for (int u = 0; u < DHH; u++) oacc += sh[u]*W2[u*DD + o];
    n_out[row*DD + o] = n3 + fmaxf(oacc, 0.f);
}

extern "C" void kernel_launch(void* const* d_in, const int* in_sizes, int n_in,
                              void* d_out, int out_size)
{
    const float* n       = (const float*)d_in[0];
    const float* e       = (const float*)d_in[1];
    const float* Wq      = (const float*)d_in[2];
    const float* Wk      = (const float*)d_in[3];
    const float* Wv      = (const float*)d_in[4];
    const float* Wo_n    = (const float*)d_in[5];
    const float* We      = (const float*)d_in[6];
    const float* Wg      = (const float*)d_in[7];
    const float* Wo_e    = (const float*)d_in[8];
    const float* ln_n1_g = (const float*)d_in[9];
    const float* ln_n1_b = (const float*)d_in[10];
    const float* ln_e1_g = (const float*)d_in[11];
    const float* ln_e1_b = (const float*)d_in[12];
    const float* ln_n2_g = (const float*)d_in[13];
    const float* ln_n2_b = (const float*)d_in[14];
    const float* ln_e2_g = (const float*)d_in[15];
    const float* ln_e2_b = (const float*)d_in[16];
    const float* mn_w1   = (const float*)d_in[17];
    const float* mn_b1   = (const float*)d_in[18];
    const float* mn_w2   = (const float*)d_in[19];
    const float* mn_b2   = (const float*)d_in[20];
    const float* me_w1   = (const float*)d_in[21];
    const float* me_b1   = (const float*)d_in[22];
    const float* me_w2   = (const float*)d_in[23];
    const float* me_b2   = (const float*)d_in[24];

    float* out   = (float*)d_out;
    float* n_out = out;
    float* e_out = out + BB*NN*DD;

    cudaFuncSetAttribute(k_edge, cudaFuncAttributeMaxDynamicSharedMemorySize, EDGE_SMEM_BYTES);
    cudaFuncSetAttribute(k_edge_finish_mlp, cudaFuncAttributeMaxDynamicSharedMemorySize, K3_SMEM_BYTES);

    k_w_prep<<<32, 256>>>(me_w1, me_w2);
    k_node_prep<<<BB*NN, 64>>>(n, Wq, Wk, Wv, ln_n1_g, ln_n1_b);

    dim3 grid2(NN, BB);
    k_edge<<<grid2, 256, EDGE_SMEM_BYTES>>>(e, We, Wg, ln_e1_g, ln_e1_b);

    dim3 grid3(8*NN, BB);
    k_edge_finish_mlp<<<grid3, 128, K3_SMEM_BYTES>>>(e, Wo_e,
                                                     ln_e1_g, ln_e1_b,
                                                     ln_e2_g, ln_e2_b,
                                                     me_b1, me_b2,
                                                     e_out);

    k_node_finish<<<BB*NN, 64>>>(Wo_n, ln_n2_g, ln_n2_b,
                                 mn_w1, mn_b1, mn_w2, mn_b2, n_out);
}

// round 17
// speedup vs baseline: 1.4185x; 1.3016x over previous
#include <cuda_runtime.h>
#include <math.h>
#include <stdint.h>

#define BB 2
#define NN 512
#define DD 64
#define HH 8
#define DHH 128

// ----------------- k_edge smem layout (floats) -----------------
#define OFF_ELOG   0
#define OFF_WEP    4160
#define OFF_WGP    4672
#define OFF_Q      5184
#define OFF_SE     5248
#define OFF_CE     5256
#define OFF_SG     5264
#define OFF_CG     5272
#define OFF_CENT   5280
#define OFF_WPART  5288
#define OFF_ET     5352
#define OFF_KT     14056
#define EDGE_SMEM_FLOATS 22760
#define EDGE_SMEM_BYTES  (EDGE_SMEM_FLOATS*4)

// ----------------- K3 v4 (bf16 mma) smem (floats/words) -----------------
#define KA_OFF    0          // sA  64 x 68 fp32        (4352)
#define KH_OFF    4352       // sH16 64 x 68 bf16x2     (4352 words)
#define KB1_OFF   8704       // 128
#define KB2_OFF   8832       // 64
#define KWOE_OFF  8896       // 512
#define KEL_OFF   9408       // 512
#define KG1_OFF   9920       // 64
#define KBE1_OFF  9984       // 64
#define KG2_OFF   10048      // 64
#define KBE2_OFF  10112      // 64
#define K3_SMEM_FLOATS 10176
#define K3_SMEM_BYTES  (K3_SMEM_FLOATS*4)   // 40704 B

__device__ __align__(16) float g_n1[BB*NN*DD];
__device__ __align__(16) float g_q [BB*NN*DD];
__device__ __align__(16) float g_k [BB*NN*DD];
__device__ __align__(16) float g_vt[BB*HH*8*NN];
__device__ __align__(16) float g_vc[BB*NN*DD];
__device__ __align__(16) float g_elog[(size_t)BB*HH*NN*NN];
__device__ __align__(16) uint32_t g_w1p[4096];   // bf16x2-packed permuted W1
__device__ __align__(16) uint32_t g_w2p[4096];   // bf16x2-packed permuted W2

// pack two floats to bf16x2: lo -> low half, hi -> high half
__device__ __forceinline__ uint32_t f2bf2(float lo, float hi) {
    uint32_t r;
    asm("cvt.rn.bf16x2.f32 %0, %1, %2;" : "=r"(r) : "f"(hi), "f"(lo));
    return r;
}

__device__ __forceinline__ void mma_bf16(float& c0, float& c1, float& c2, float& c3,
                                         uint32_t a0, uint32_t a1,
                                         uint32_t a2, uint32_t a3,
                                         uint32_t b0, uint32_t b1) {
    asm volatile(
        "mma.sync.aligned.m16n8k16.row.col.f32.bf16.bf16.f32 "
        "{%0,%1,%2,%3},{%4,%5,%6,%7},{%8,%9},{%0,%1,%2,%3};"
        : "+f"(c0), "+f"(c1), "+f"(c2), "+f"(c3)
        : "r"(a0), "r"(a1), "r"(a2), "r"(a3), "r"(b0), "r"(b1));
}

// ---------------------------------------------------------------------------
// K0: pack W1/W2 into bf16x2 fragment-ready layout.
// word(s,tig,khalf,p) at ((s*4+tig)*2+khalf)*Nw + p,  p = nc*32+gid*4+nt,
// logical n = nc*32 + nt*8 + gid, k0 = s*16 + khalf*8 + 2*tig,
// value = pack(W[k0][n], W[k0+1][n]).
// ---------------------------------------------------------------------------
__global__ void k_w_prep(const float* __restrict__ W1, const float* __restrict__ W2)
{
    int t = blockIdx.x*256 + threadIdx.x;
    if (t < 4096) {
        {   // W1: 4 ksteps x 128 n
            int row = t >> 7;             // 0..31
            int p   = t & 127;
            int khalf = row & 1, tig = (row >> 1) & 3, s = row >> 3;
            int nc = p >> 5, r = p & 31, gid = r >> 2, nt = r & 3;
            int nl = nc*32 + nt*8 + gid;
            int k0 = s*16 + khalf*8 + 2*tig;
            g_w1p[t] = f2bf2(W1[k0*DHH + nl], W1[(k0+1)*DHH + nl]);
        }
        {   // W2: 8 ksteps x 64 n
            int row = t >> 6;             // 0..63
            int p   = t & 63;
            int khalf = row & 1, tig = (row >> 1) & 3, s = row >> 3;
            int nc = p >> 5, r = p & 31, gid = r >> 2, nt = r & 3;
            int nl = nc*32 + nt*8 + gid;
            int k0 = s*16 + khalf*8 + 2*tig;
            g_w2p[t] = f2bf2(W2[k0*64 + nl], W2[(k0+1)*64 + nl]);
        }
    }
}

// ---------------------------------------------------------------------------
// K1: node LN + Q/K/V projection (V also stored transposed).
// ---------------------------------------------------------------------------
__global__ void k_node_prep(const float* __restrict__ n,
                            const float* __restrict__ Wq,
                            const float* __restrict__ Wk,
                            const float* __restrict__ Wv,
                            const float* __restrict__ lng,
                            const float* __restrict__ lnb)
{
    int row = blockIdx.x;
    int o = threadIdx.x;
    __shared__ float sx[DD];
    __shared__ float sn1[DD];
    sx[o] = n[row*DD + o];
    __syncthreads();
    float s = 0.f;
    #pragma unroll
    for (int k = 0; k < DD; k++) s += sx[k];
    float m = s * (1.f/DD);
    float v = 0.f;
    #pragma unroll
    for (int k = 0; k < DD; k++) { float d = sx[k]-m; v += d*d; }
    v *= (1.f/DD);
    float rstd = rsqrtf(v + 1e-5f);
    float n1 = (sx[o]-m)*rstd*lng[o] + lnb[o];
    sn1[o] = n1;
    g_n1[row*DD + o] = n1;
    __syncthreads();
    float q = 0.f, kk = 0.f, vv = 0.f;
    #pragma unroll
    for (int k = 0; k < DD; k++) {
        float a = sn1[k];
        q  += a * Wq[k*DD + o];
        kk += a * Wk[k*DD + o];
        vv += a * Wv[k*DD + o];
    }
    g_q[row*DD + o] = q;
    g_k[row*DD + o] = kk;
    int b = row >> 9;
    int j = row & 511;
    int h = o >> 3;
    int d = o & 7;
    g_vt[((b*HH + h)*8 + d)*NN + j] = vv;
}

// ---------------------------------------------------------------------------
// K2: edge attention (byte-identical to the 628us build).
// ---------------------------------------------------------------------------
__global__ void __launch_bounds__(256, 1)
k_edge(const float* __restrict__ e,
       const float* __restrict__ We, const float* __restrict__ Wg,
       const float* __restrict__ lg1, const float* __restrict__ lb1)
{
    extern __shared__ float sm[];
    float* sElog  = sm + OFF_ELOG;
    float* sWeP   = sm + OFF_WEP;
    float* sWgP   = sm + OFF_WGP;
    float* sQ     = sm + OFF_Q;
    float* sSe    = sm + OFF_SE;
    float* sCe    = sm + OFF_CE;
    float* sSg    = sm + OFF_SG;
    float* sCg    = sm + OFF_CG;
    float* sCent  = sm + OFF_CENT;
    float* sWpart = sm + OFF_WPART;
    float* sE     = sm + OFF_ET;
    float* sK     = sm + OFF_KT;

    const int i    = blockIdx.x;
    const int b    = blockIdx.y;
    const int tid  = threadIdx.x;
    const int lane = tid & 31;
    const int warp = tid >> 5;
    const int rowbn = b*NN + i;

    const int r    = tid >> 1;
    const int half = tid & 1;
    const int k0w  = half * 32;

    for (int t = tid; t < 512; t += 256) {
        int k = t >> 3;
        float g = lg1[k];
        sWeP[t] = g * We[t];
        sWgP[t] = g * Wg[t];
    }
    if (tid < 64) sQ[tid] = g_q[rowbn*DD + tid];
    __syncthreads();
    if (tid < 8) {
        float se=0.f, ce=0.f, sg=0.f, cg=0.f;
        for (int k = 0; k < 64; k++) {
            float bb = lb1[k];
            se += sWeP[k*8 + tid];
            sg += sWgP[k*8 + tid];
            ce += bb * We[k*8 + tid];
            cg += bb * Wg[k*8 + tid];
        }
        sSe[tid]=se; sCe[tid]=ce; sSg[tid]=sg; sCg[tid]=cg;
    }

    const float scale = 0.35355339059327373f;
    float gacc[HH];
    #pragma unroll
    for (int h = 0; h < HH; h++) gacc[h] = 0.f;

    for (int ch = 0; ch < 4; ch++) {
        const int j0 = ch*128;
        __syncthreads();
        for (int t = tid; t < 2048; t += 256) {
            int row = t >> 4, q = t & 15;
            *(float4*)(sE + row*68 + q*4) =
                *(const float4*)(e + ((size_t)rowbn*NN + j0 + row)*DD + q*4);
            *(float4*)(sK + row*68 + q*4) =
                *(const float4*)(g_k + ((size_t)b*NN + j0 + row)*DD + q*4);
        }
        __syncthreads();

        float s = 0.f, sq = 0.f;
        float Eh[HH], Gh[HH];
        #pragma unroll
        for (int h = 0; h < HH; h++) { Eh[h]=0.f; Gh[h]=0.f; }
        float ac0=0.f, ac1=0.f, ac2=0.f, ac3=0.f;

        const float4* xp = (const float4*)(sE + r*68 + k0w);
        const float4* kp = (const float4*)(sK + r*68 + k0w);
        const float4* qp = (const float4*)(sQ + k0w);

        #pragma unroll
        for (int q = 0; q < 8; q++) {
            float4 xv = xp[q];
            float4 kv = kp[q];
            float4 qv = qp[q];
            s  += (xv.x + xv.y) + (xv.z + xv.w);
            sq += (xv.x*xv.x + xv.y*xv.y) + (xv.z*xv.z + xv.w*xv.w);
            float dot = qv.x*kv.x + qv.y*kv.y + qv.z*kv.z + qv.w*kv.w;
            if (q < 2)      ac0 += dot;
            else if (q < 4) ac1 += dot;
            else if (q < 6) ac2 += dot;
            else            ac3 += dot;
            float xs[4] = {xv.x, xv.y, xv.z, xv.w};
            #pragma unroll
            for (int c = 0; c < 4; c++) {
                int k = k0w + q*4 + c;
                float xk = xs[c];
                const float4* we = (const float4*)(sWeP + k*8);
                const float4* wg = (const float4*)(sWgP + k*8);
                float4 a0 = we[0], a1 = we[1];
                float4 c0 = wg[0], c1 = wg[1];
                Eh[0]+=xk*a0.x; Eh[1]+=xk*a0.y; Eh[2]+=xk*a0.z; Eh[3]+=xk*a0.w;
                Eh[4]+=xk*a1.x; Eh[5]+=xk*a1.y; Eh[6]+=xk*a1.z; Eh[7]+=xk*a1.w;
                Gh[0]+=xk*c0.x; Gh[1]+=xk*c0.y; Gh[2]+=xk*c0.z; Gh[3]+=xk*c0.w;
                Gh[4]+=xk*c1.x; Gh[5]+=xk*c1.y; Gh[6]+=xk*c1.z; Gh[7]+=xk*c1.w;
            }
        }

        s  += __shfl_xor_sync(0xffffffffu, s, 1);
        sq += __shfl_xor_sync(0xffffffffu, sq, 1);
        #pragma unroll
        for (int h = 0; h < HH; h++) {
            Eh[h] += __shfl_xor_sync(0xffffffffu, Eh[h], 1);
            Gh[h] += __shfl_xor_sync(0xffffffffu, Gh[h], 1);
        }
        float p0 = __shfl_xor_sync(0xffffffffu, ac0, 1);
        float p1 = __shfl_xor_sync(0xffffffffu, ac1, 1);
        float p2 = __shfl_xor_sync(0xffffffffu, ac2, 1);
        float p3 = __shfl_xor_sync(0xffffffffu, ac3, 1);
        float qk0 = half ? p0 : ac0;
        float qk1 = half ? p1 : ac1;
        float qk2 = half ? p2 : ac2;
        float qk3 = half ? p3 : ac3;
        float qk4 = half ? ac0 : p0;
        float qk5 = half ? ac1 : p1;
        float qk6 = half ? ac2 : p2;
        float qk7 = half ? ac3 : p3;

        float m = s * (1.f/64.f);
        float var = sq * (1.f/64.f) - m*m;
        float rstd = rsqrtf(var + 1e-5f);

        if (half == 0) {
            const int j = j0 + r;
            float qks[8] = {qk0,qk1,qk2,qk3,qk4,qk5,qk6,qk7};
            #pragma unroll
            for (int h = 0; h < HH; h++) {
                float E = rstd*(Eh[h] - m*sSe[h]) + sCe[h];
                float G = rstd*(Gh[h] - m*sSg[h]) + sCg[h];
                float a = fminf(fmaxf(qks[h]*scale, -5.f), 5.f);
                sElog[h*520 + j] = a + E;
                gacc[h] += 1.f/(1.f + expf(-G));
            }
        }
    }

    #pragma unroll
    for (int h = 0; h < HH; h++) {
        #pragma unroll
        for (int off = 16; off > 0; off >>= 1)
            gacc[h] += __shfl_xor_sync(0xffffffffu, gacc[h], off);
    }
    if (lane == 0) {
        #pragma unroll
        for (int h = 0; h < HH; h++) sWpart[warp*8 + h] = gacc[h];
    }
    __syncthreads();
    if (tid < 8) {
        float ssum = 0.f;
        #pragma unroll
        for (int w = 0; w < 8; w++) ssum += sWpart[w*8 + tid];
        sCent[tid] = log1pf(ssum);
    }
    __syncthreads();

    {
        const int h = warp;
        const float* el = sElog + h*520;
        const float* vt = g_vt + (size_t)(b*HH + h)*8*NN;
        float mmax = -1e30f;
        for (int j = lane; j < NN; j += 32) mmax = fmaxf(mmax, el[j]);
        #pragma unroll
        for (int off = 16; off > 0; off >>= 1)
            mmax = fmaxf(mmax, __shfl_xor_sync(0xffffffffu, mmax, off));

        float denom = 0.f;
        float p0=0,p1=0,p2=0,p3=0,p4=0,p5=0,p6=0,p7=0;
        for (int j = lane; j < NN; j += 32) {
            float t = expf(el[j] - mmax);
            denom += t;
            p0 += t*vt[0*NN + j];
            p1 += t*vt[1*NN + j];
            p2 += t*vt[2*NN + j];
            p3 += t*vt[3*NN + j];
            p4 += t*vt[4*NN + j];
            p5 += t*vt[5*NN + j];
            p6 += t*vt[6*NN + j];
            p7 += t*vt[7*NN + j];
        }
        #pragma unroll
        for (int off = 16; off > 0; off >>= 1) {
            denom += __shfl_xor_sync(0xffffffffu, denom, off);
            p0 += __shfl_xor_sync(0xffffffffu, p0, off);
            p1 += __shfl_xor_sync(0xffffffffu, p1, off);
            p2 += __shfl_xor_sync(0xffffffffu, p2, off);
            p3 += __shfl_xor_sync(0xffffffffu, p3, off);
            p4 += __shfl_xor_sync(0xffffffffu, p4, off);
            p5 += __shfl_xor_sync(0xffffffffu, p5, off);
            p6 += __shfl_xor_sync(0xffffffffu, p6, off);
            p7 += __shfl_xor_sync(0xffffffffu, p7, off);
        }
        if (lane == 0) {
            float c = sCent[h] / denom;
            float* dst = g_vc + rowbn*DD + h*8;
            dst[0]=p0*c; dst[1]=p1*c; dst[2]=p2*c; dst[3]=p3*c;
            dst[4]=p4*c; dst[5]=p5*c; dst[6]=p6*c; dst[7]=p7*c;
        }
    }

    __syncthreads();
    for (int t = tid; t < HH*NN; t += 256) {
        int h = t >> 9, j = t & 511;
        g_elog[(((size_t)b*HH + h)*NN + i)*NN + j] = sElog[h*520 + j];
    }
}

// ---------------------------------------------------------------------------
// K3 v4: fused edge finish + MLP, bf16 m16n8k16 mma.
// 128 threads, 64-edge tile, gmem bf16 weights, 40.7KB smem.
// ---------------------------------------------------------------------------
__global__ void __launch_bounds__(128, 1)
k_edge_finish_mlp(const float* __restrict__ e,
                  const float* __restrict__ WoE,
                  const float* __restrict__ lg1, const float* __restrict__ lb1,
                  const float* __restrict__ lg2, const float* __restrict__ lb2,
                  const float* __restrict__ b1, const float* __restrict__ b2,
                  float* __restrict__ e_out)
{
    extern __shared__ float sm[];
    float*    sA   = sm + KA_OFF;               // fp32 [64][68]
    uint32_t* sH16 = (uint32_t*)(sm + KH_OFF);  // bf16x2 [64][68]
    float*    sB1  = sm + KB1_OFF;
    float*    sB2  = sm + KB2_OFF;
    float*    sWoe = sm + KWOE_OFF;
    float*    sEl  = sm + KEL_OFF;
    float*    sG1  = sm + KG1_OFF;
    float*    sBe1 = sm + KBE1_OFF;
    float*    sG2  = sm + KG2_OFF;
    float*    sBe2 = sm + KBE2_OFF;

    const int tid  = threadIdx.x;
    const int lane = tid & 31;
    const int warp = tid >> 5;
    const int gid  = lane >> 2;
    const int tig  = lane & 3;

    const int bx = blockIdx.x;
    const int jc = bx & 7;
    const int i  = bx >> 3;
    const int b  = blockIdx.y;
    const int rowbn = b*NN + i;
    const size_t gj0 = (size_t)rowbn*NN + jc*64;

    for (int t = tid; t < 512; t += 128) sWoe[t] = WoE[t];
    if (tid < 128) sB1[tid] = b1[tid];
    if (tid < 64) {
        sB2[tid]  = b2[tid];
        sG1[tid]  = lg1[tid]; sBe1[tid] = lb1[tid];
        sG2[tid]  = lg2[tid]; sBe2[tid] = lb2[tid];
    }
    for (int t = tid; t < 512; t += 128) {
        int h = t >> 6, jl = t & 63;
        sEl[h*64 + jl] = g_elog[(((size_t)b*HH + h)*NN + i)*NN + jc*64 + jl];
    }
    for (int t = tid; t < 64*16; t += 128) {
        int row = t >> 4, q = t & 15;
        float4 v = *(const float4*)(e + (gj0 + row)*DD + q*4);
        *(float4*)(sA + row*68 + q*4) = v;
    }
    __syncthreads();

    // phase A: e3 = LN2( LN1(x) + El@WoE ) in place in sA
    {
        const int r     = tid >> 1;
        const int halfc = tid & 1;
        const int c0    = halfc*32;

        float s = 0.f, sq = 0.f;
        #pragma unroll
        for (int c = 0; c < 32; c++) {
            float v = sA[r*68 + c0 + c];
            s += v; sq += v*v;
        }
        s  += __shfl_xor_sync(0xffffffffu, s, 1);
        sq += __shfl_xor_sync(0xffffffffu, sq, 1);
        float m = s*(1.f/64.f);
        float rstd = rsqrtf(sq*(1.f/64.f) - m*m + 1e-5f);

        float el0=sEl[r],     el1=sEl[64+r],  el2=sEl[128+r], el3=sEl[192+r];
        float el4=sEl[256+r], el5=sEl[320+r], el6=sEl[384+r], el7=sEl[448+r];

        float s2 = 0.f, q2 = 0.f;
        #pragma unroll
        for (int c = 0; c < 32; c++) {
            int k = c0 + c;
            float x = sA[r*68 + k];
            float a = (x - m)*rstd*sG1[k] + sBe1[k];
            a += el0*sWoe[k]       + el1*sWoe[64 + k]
               + el2*sWoe[128 + k] + el3*sWoe[192 + k]
               + el4*sWoe[256 + k] + el5*sWoe[320 + k]
               + el6*sWoe[384 + k] + el7*sWoe[448 + k];
            s2 += a; q2 += a*a;
            sA[r*68 + k] = a;
        }
        s2 += __shfl_xor_sync(0xffffffffu, s2, 1);
        q2 += __shfl_xor_sync(0xffffffffu, q2, 1);
        float m2 = s2*(1.f/64.f);
        float rstd2 = rsqrtf(q2*(1.f/64.f) - m2*m2 + 1e-5f);
        __syncwarp();
        #pragma unroll
        for (int c = 0; c < 32; c++) {
            int k = c0 + c;
            float y = sA[r*68 + k];
            sA[r*68 + k] = (y - m2)*rstd2*sG2[k] + sBe2[k];
        }
    }
    __syncthreads();

    // phase B: bf16 mma MLP
    const int row0 = warp*16 + gid;
    const int row1 = row0 + 8;

    // A fragments for GEMM1: 4 ksteps x 4 regs (bf16x2)
    uint32_t A0[4], A1[4], A2[4], A3[4];
    #pragma unroll
    for (int s = 0; s < 4; s++) {
        int c0 = s*16 + 2*tig;
        A0[s] = f2bf2(sA[row0*68 + c0],     sA[row0*68 + c0 + 1]);
        A1[s] = f2bf2(sA[row1*68 + c0],     sA[row1*68 + c0 + 1]);
        A2[s] = f2bf2(sA[row0*68 + c0 + 8], sA[row0*68 + c0 + 9]);
        A3[s] = f2bf2(sA[row1*68 + c0 + 8], sA[row1*68 + c0 + 9]);
    }

    // GEMM1: H = relu(A @ W1 + b1), N=128 in 4 chunks of 32
    #pragma unroll
    for (int nc = 0; nc < 4; nc++) {
        float a00=0,a01=0,a02=0,a03=0;
        float a10=0,a11=0,a12=0,a13=0;
        float a20=0,a21=0,a22=0,a23=0;
        float a30=0,a31=0,a32=0,a33=0;
        #pragma unroll
        for (int s = 0; s < 4; s++) {
            const uint4 bv0 = *(const uint4*)(g_w1p + ((s*4 + tig)*2 + 0)*128 + nc*32 + gid*4);
            const uint4 bv1 = *(const uint4*)(g_w1p + ((s*4 + tig)*2 + 1)*128 + nc*32 + gid*4);
            mma_bf16(a00,a01,a02,a03, A0[s],A1[s],A2[s],A3[s], bv0.x,bv1.x);
            mma_bf16(a10,a11,a12,a13, A0[s],A1[s],A2[s],A3[s], bv0.y,bv1.y);
            mma_bf16(a20,a21,a22,a23, A0[s],A1[s],A2[s],A3[s], bv0.z,bv1.z);
            mma_bf16(a30,a31,a32,a33, A0[s],A1[s],A2[s],A3[s], bv0.w,bv1.w);
        }
        #pragma unroll
        for (int nt = 0; nt < 4; nt++) {
            float c0v, c1v, c2v, c3v;
            if (nt == 0)      { c0v=a00; c1v=a01; c2v=a02; c3v=a03; }
            else if (nt == 1) { c0v=a10; c1v=a11; c2v=a12; c3v=a13; }
            else if (nt == 2) { c0v=a20; c1v=a21; c2v=a22; c3v=a23; }
            else              { c0v=a30; c1v=a31; c2v=a32; c3v=a33; }
            int c = nc*32 + nt*8 + 2*tig;
            float bb0 = sB1[c], bb1 = sB1[c+1];
            sH16[row0*68 + (c >> 1)] = f2bf2(fmaxf(c0v + bb0, 0.f), fmaxf(c1v + bb1, 0.f));
            sH16[row1*68 + (c >> 1)] = f2bf2(fmaxf(c2v + bb0, 0.f), fmaxf(c3v + bb1, 0.f));
        }
    }
    __syncwarp();

    // GEMM2: O = H @ W2 + b2, N=64 in 2 chunks of 32; H read as packed bf16x2
    #pragma unroll
    for (int nc = 0; nc < 2; nc++) {
        float a00=0,a01=0,a02=0,a03=0;
        float a10=0,a11=0,a12=0,a13=0;
        float a20=0,a21=0,a22=0,a23=0;
        float a30=0,a31=0,a32=0,a33=0;
        #pragma unroll
        for (int s = 0; s < 8; s++) {
            uint32_t h0 = sH16[row0*68 + 8*s + tig];
            uint32_t h1 = sH16[row1*68 + 8*s + tig];
            uint32_t h2 = sH16[row0*68 + 8*s + 4 + tig];
            uint32_t h3 = sH16[row1*68 + 8*s + 4 + tig];
            const uint4 bv0 = *(const uint4*)(g_w2p + ((s*4 + tig)*2 + 0)*64 + nc*32 + gid*4);
            const uint4 bv1 = *(const uint4*)(g_w2p + ((s*4 + tig)*2 + 1)*64 + nc*32 + gid*4);
            mma_bf16(a00,a01,a02,a03, h0,h1,h2,h3, bv0.x,bv1.x);
            mma_bf16(a10,a11,a12,a13, h0,h1,h2,h3, bv0.y,bv1.y);
            mma_bf16(a20,a21,a22,a23, h0,h1,h2,h3, bv0.z,bv1.z);
            mma_bf16(a30,a31,a32,a33, h0,h1,h2,h3, bv0.w,bv1.w);
        }
        #pragma unroll
        for (int nt = 0; nt < 4; nt++) {
            float c0v, c1v, c2v, c3v;
            if (nt == 0)      { c0v=a00; c1v=a01; c2v=a02; c3v=a03; }
            else if (nt == 1) { c0v=a10; c1v=a11; c2v=a12; c3v=a13; }
            else if (nt == 2) { c0v=a20; c1v=a21; c2v=a22; c3v=a23; }
            else              { c0v=a30; c1v=a31; c2v=a32; c3v=a33; }
            int c = nc*32 + nt*8 + 2*tig;
            float b20v = sB2[c], b21v = sB2[c+1];
            float r00 = sA[row0*68 + c    ] + fmaxf(c0v + b20v, 0.f);
            float r01 = sA[row0*68 + c + 1] + fmaxf(c1v + b21v, 0.f);
            float r10 = sA[row1*68 + c    ] + fmaxf(c2v + b20v, 0.f);
            float r11 = sA[row1*68 + c + 1] + fmaxf(c3v + b21v, 0.f);
            *(float2*)(e_out + (gj0 + row0)*DD + c) = make_float2(r00, r01);
            *(float2*)(e_out + (gj0 + row1)*DD + c) = make_float2(r10, r11);
        }
    }
}

// ---------------------------------------------------------------------------
// K4: node finish.
// ---------------------------------------------------------------------------
__global__ void k_node_finish(const float* __restrict__ Wo_n,
                              const float* __restrict__ lng,
                              const float* __restrict__ lnb,
                              const float* __restrict__ W1,
                              const float* __restrict__ Bi1,
                              const float* __restrict__ W2,
                              const float* __restrict__ Bi2,
                              float* __restrict__ n_out)
{
    int row = blockIdx.x;
    int o = threadIdx.x;
    __shared__ float svc[DD];
    __shared__ float sn2[DD];
    __shared__ float sn3[DD];
    __shared__ float sh[DHH];
    svc[o] = g_vc[row*DD + o];
    __syncthreads();
    float acc = 0.f;
    #pragma unroll
    for (int k = 0; k < DD; k++) acc += svc[k]*Wo_n[k*DD + o];
    float n2 = g_n1[row*DD + o] + acc;
    sn2[o] = n2;
    __syncthreads();
    float s = 0.f;
    #pragma unroll
    for (int k = 0; k < DD; k++) s += sn2[k];
    float m = s*(1.f/DD);
    float v = 0.f;
    #pragma unroll
    for (int k = 0; k < DD; k++) { float d = sn2[k]-m; v += d*d; }
    v *= (1.f/DD);
    float rstd = rsqrtf(v + 1e-5f);
    float n3 = (n2-m)*rstd*lng[o] + lnb[o];
    sn3[o] = n3;
    __syncthreads();
    #pragma unroll
    for (int uu = 0; uu < 2; uu++) {
        int u = o + uu*64;
        float h = Bi1[u];
        #pragma unroll
        for (int k = 0; k < DD; k++) h += sn3[k]*W1[k*DHH + u];
        sh[u] = fmaxf(h, 0.f);
    }
    __syncthreads();
    float oacc = Bi2[o];
    #pragma unroll
    for (int u = 0; u < DHH; u++) oacc += sh[u]*W2[u*DD + o];
    n_out[row*DD + o] = n3 + fmaxf(oacc, 0.f);
}

extern "C" void kernel_launch(void* const* d_in, const int* in_sizes, int n_in,
                              void* d_out, int out_size)
{
    const float* n       = (const float*)d_in[0];
    const float* e       = (const float*)d_in[1];
    const float* Wq      = (const float*)d_in[2];
    const float* Wk      = (const float*)d_in[3];
    const float* Wv      = (const float*)d_in[4];
    const float* Wo_n    = (const float*)d_in[5];
    const float* We      = (const float*)d_in[6];
    const float* Wg      = (const float*)d_in[7];
    const float* Wo_e    = (const float*)d_in[8];
    const float* ln_n1_g = (const float*)d_in[9];
    const float* ln_n1_b = (const float*)d_in[10];
    const float* ln_e1_g = (const float*)d_in[11];
    const float* ln_e1_b = (const float*)d_in[12];
    const float* ln_n2_g = (const float*)d_in[13];
    const float* ln_n2_b = (const float*)d_in[14];
    const float* ln_e2_g = (const float*)d_in[15];
    const float* ln_e2_b = (const float*)d_in[16];
    const float* mn_w1   = (const float*)d_in[17];
    const float* mn_b1   = (const float*)d_in[18];
    const float* mn_w2   = (const float*)d_in[19];
    const float* mn_b2   = (const float*)d_in[20];
    const float* me_w1   = (const float*)d_in[21];
    const float* me_b1   = (const float*)d_in[22];
    const float* me_w2   = (const float*)d_in[23];
    const float* me_b2   = (const float*)d_in[24];

    float* out   = (float*)d_out;
    float* n_out = out;
    float* e_out = out + BB*NN*DD;

    cudaFuncSetAttribute(k_edge, cudaFuncAttributeMaxDynamicSharedMemorySize, EDGE_SMEM_BYTES);
    cudaFuncSetAttribute(k_edge_finish_mlp, cudaFuncAttributeMaxDynamicSharedMemorySize, K3_SMEM_BYTES);

    k_w_prep<<<16, 256>>>(me_w1, me_w2);
    k_node_prep<<<BB*NN, 64>>>(n, Wq, Wk, Wv, ln_n1_g, ln_n1_b);

    dim3 grid2(NN, BB);
    k_edge<<<grid2, 256, EDGE_SMEM_BYTES>>>(e, We, Wg, ln_e1_g, ln_e1_b);

    dim3 grid3(8*NN, BB);
    k_edge_finish_mlp<<<grid3, 128, K3_SMEM_BYTES>>>(e, Wo_e,
                                                     ln_e1_g, ln_e1_b,
                                                     ln_e2_g, ln_e2_b,
                                                     me_b1, me_b2,
                                                     e_out);

    k_node_finish<<<BB*NN, 64>>>(Wo_n, ln_n2_g, ln_n2_b,
                                 mn_w1, mn_b1, mn_w2, mn_b2, n_out);
}